// round 14
// baseline (speedup 1.0000x reference)
#include <cuda_runtime.h>
#include <cuda_fp16.h>
#include <math.h>

// RandomLowRes2D fused kernel, v11: fp16 pair-major A with AS2 % 32 == 9
// padding (conflict-free blur for res strides 1/2/4/8, no swizzle ALU),
// immediate-offset tap loads, fp32 accumulation, fp16 pos-major LOW,
// 10 CTAs/SM, fused blur+downsample, image-interleaved CTAs.

#define HDIM 512
#define TW   8            // lanes (cross-axis) per CTA
#define HALO 16
#define NROW (HDIM + 2 * HALO)   // 544 logical rows
#define AS2  553          // A pair-row stride in half2 units; 553 % 32 == 9
#define NT   128

__device__ __forceinline__ int refl(int t) {
    t = (t < 0) ? (-1 - t) : t;
    return (t >= HDIM) ? (2 * HDIM - 1 - t) : t;
}

// Fused blur+downsample. Task = (lane-pair q, low row j). One half2 load per
// tap row (immediate offset), feeding 2 lanes x 2 row-accumulators (fp32).
template<int R>
__device__ __forceinline__ void blur_down(const __half2* __restrict__ A2,
                                          __half* __restrict__ LOW,
                                          const float* __restrict__ w,
                                          float inv_wsum, float res,
                                          int n_low, int tid)
{
    float wr[R + 1];
    if (R == 0) wr[0] = 1.0f;
    else {
        #pragma unroll
        for (int k = 0; k <= R; k++) wr[k] = w[15 - R + k] * inv_wsum;
    }
    const int ntask = n_low * 4;
    for (int task = tid; task < ntask; task += NT) {
        int q = task & 3;
        int j = task >> 2;
        float pos = fminf((float)j * res, 511.0f);
        float lof = floorf(pos);
        float fr  = pos - lof;
        int   p1  = (int)lof;
        const __half2* Ap = A2 + q * AS2 + (HALO + p1 - R);  // one base, imm offsets
        float a0x = 0.f, a0y = 0.f, a1x = 0.f, a1y = 0.f;
        #pragma unroll
        for (int k = 0; k <= 2 * R + 1; k++) {
            float2 v = __half22float2(Ap[k]);
            if (k <= 2 * R) {
                float w0 = wr[(k <= R) ? k : 2 * R - k];
                a0x = fmaf(w0, v.x, a0x);
                a0y = fmaf(w0, v.y, a0y);
            }
            if (k >= 1) {
                int km = k - 1;
                float w1 = wr[(km <= R) ? km : 2 * R - km];
                a1x = fmaf(w1, v.x, a1x);
                a1y = fmaf(w1, v.y, a1y);
            }
        }
        float f0 = 1.0f - fr;
        __half2 o = __floats2half2_rn(a0x * f0 + a1x * fr,
                                      a0y * f0 + a1y * fr);
        *(__half2*)(LOW + j * TW + 2 * q) = o;   // bank 4j+q: conflict-free
    }
}

__global__ __launch_bounds__(NT, 10)
void lowres_kernel(const float* __restrict__ x,
                   const float* __restrict__ resolution,
                   const int*   __restrict__ axis,
                   const float* __restrict__ gap,
                   float* __restrict__ out)
{
    extern __shared__ float dynsm[];
    __half2* A2   = (__half2*)dynsm;                 // [4][AS2] half2 (8848 B)
    __half*  A_h  = (__half*)A2;
    __half*  LOW  = (__half*)(A2 + 4 * AS2);         // [HDIM][8] fp16 (8192 B)
    float*   pos2 = (float*)(LOW + HDIM * TW);       // [HDIM]
    float*   w    = pos2 + HDIM;                     // [32]

    const int bid  = blockIdx.x;
    const int img  = bid & 63;          // interleave images across waves
    const int tile = bid >> 6;
    const int tid  = threadIdx.x;

    const float res = resolution[img];
    const int   ax  = axis[img];
    const float sig = fmaxf(res * gap[img] * 0.42466090014400953f, 1e-6f);
    const int   R   = (sig < 0.18f) ? 0 : (sig < 0.6f) ? 3 : (sig < 1.4f) ? 7 : 15;

    const int   n_low = (int)fmaxf(floorf(512.0f / res), 1.0f);
    const float nl1   = (float)(n_low - 1);

    if (tid < 31) {
        float e = (float)(tid - 15) / sig;
        w[tid] = expf(-0.5f * e * e);
    }
    for (int i = tid; i < HDIM; i += NT)
        pos2[i] = fminf((float)i / res, nl1);   // true division as reference

    const int base = tile * TW;
    const size_t ib = (size_t)img * HDIM * HDIM;
    const float* ip = x + ib;
    float*       op = out + ib;

    // ---- load slab into fp16 pair-major A (+ reflected halo) ----
    if (ax == 0) {
        const float4* ip4 = (const float4*)ip;
        for (int idx = tid; idx < HDIM * 2; idx += NT) {
            int l4 = idx & 1;                  // lanes 4*l4 .. 4*l4+3
            int p  = idx >> 1;
            float4 v = ip4[p * (HDIM / 4) + (base >> 2) + l4];
            int q0 = 2 * l4;
            A2[q0 * AS2 + HALO + p]       = __floats2half2_rn(v.x, v.y);
            A2[(q0 + 1) * AS2 + HALO + p] = __floats2half2_rn(v.z, v.w);
        }
    } else {
        // warp = 8 lanes x 4 col-groups: scalar half stores <=2-way
        for (int idx = tid; idx < TW * (HDIM / 4); idx += NT) {
            int l = idx & 7;
            int v = idx >> 3;
            float4 t = *(const float4*)(ip + (size_t)(base + l) * HDIM + 4 * v);
            int q = l >> 1, h = l & 1;
            #pragma unroll
            for (int i = 0; i < 4; i++) {
                int row = 4 * v + i + HALO;
                float val = (i == 0) ? t.x : (i == 1) ? t.y : (i == 2) ? t.z : t.w;
                A_h[(q * AS2 + row) * 2 + h] = __float2half(val);
            }
        }
    }
    for (int idx = tid; idx < 2 * HALO * TW; idx += NT) {   // 256 halo elems
        int l = idx & (TW - 1);
        int hh = idx >> 3;
        int t = (hh < HALO) ? (hh - HALO) : (HDIM + hh - HALO);
        int rt = refl(t);
        float val = (ax == 0) ? ip[rt * HDIM + base + l]
                              : ip[(size_t)(base + l) * HDIM + rt];
        A_h[((l >> 1) * AS2 + HALO + t) * 2 + (l & 1)] = __float2half(val);
    }
    __syncthreads();

    float inv_wsum = 1.0f;
    if (R > 0) {
        float s = 0.f;
        #pragma unroll
        for (int k = 0; k < 31; k++) s += w[k];
        inv_wsum = 1.0f / s;
    }

    // ---- fused blur + downsample -> LOW (fp16, pos-major) ----
    if      (R == 0)  blur_down<0>(A2, LOW, w, inv_wsum, res, n_low, tid);
    else if (R == 3)  blur_down<3>(A2, LOW, w, inv_wsum, res, n_low, tid);
    else if (R == 7)  blur_down<7>(A2, LOW, w, inv_wsum, res, n_low, tid);
    else              blur_down<15>(A2, LOW, w, inv_wsum, res, n_low, tid);
    __syncthreads();

    // ---- upsample + gmem stores ----
    if (ax == 0) {
        for (int i = tid; i < HDIM; i += NT) {
            float p2v = pos2[i];
            float l2  = floorf(p2v);
            float f   = p2v - l2;
            int j1 = min((int)l2, n_low - 1);
            int j2 = min(j1 + 1, n_low - 1);
            float omf = 1.0f - f;
            float4 r1 = *(const float4*)(LOW + j1 * TW);   // whole 8-lane row
            float4 r2 = *(const float4*)(LOW + j2 * TW);
            const __half2* h1 = (const __half2*)&r1;
            const __half2* h2 = (const __half2*)&r2;
            float4 o0, o1;
            {
                float2 a = __half22float2(h1[0]), b = __half22float2(h2[0]);
                o0.x = a.x * omf + b.x * f;  o0.y = a.y * omf + b.y * f;
                a = __half22float2(h1[1]); b = __half22float2(h2[1]);
                o0.z = a.x * omf + b.x * f;  o0.w = a.y * omf + b.y * f;
                a = __half22float2(h1[2]); b = __half22float2(h2[2]);
                o1.x = a.x * omf + b.x * f;  o1.y = a.y * omf + b.y * f;
                a = __half22float2(h1[3]); b = __half22float2(h2[3]);
                o1.z = a.x * omf + b.x * f;  o1.w = a.y * omf + b.y * f;
            }
            *(float4*)(op + (size_t)i * HDIM + base)     = o0;
            *(float4*)(op + (size_t)i * HDIM + base + 4) = o1;
        }
    } else {
        for (int idx = tid; idx < 4 * (HDIM / 4); idx += NT) {
            int v  = idx & 127;
            int lq = idx >> 7;              // 0..3 -> lanes 2lq, 2lq+1
            const float4 pv = *(const float4*)(pos2 + 4 * v);
            float4 ra, rb;
            #pragma unroll
            for (int q = 0; q < 4; q++) {
                float p2v = (q == 0) ? pv.x : (q == 1) ? pv.y : (q == 2) ? pv.z : pv.w;
                float l2  = floorf(p2v);
                float f   = p2v - l2;
                int j1 = min((int)l2, n_low - 1);
                int j2 = min(j1 + 1, n_low - 1);
                float2 h1 = __half22float2(*(const __half2*)(LOW + j1 * TW + 2 * lq));
                float2 h2 = __half22float2(*(const __half2*)(LOW + j2 * TW + 2 * lq));
                float va = h1.x * (1.0f - f) + h2.x * f;
                float vb = h1.y * (1.0f - f) + h2.y * f;
                if (q == 0) { ra.x = va; rb.x = vb; }
                else if (q == 1) { ra.y = va; rb.y = vb; }
                else if (q == 2) { ra.z = va; rb.z = vb; }
                else { ra.w = va; rb.w = vb; }
            }
            *(float4*)(op + (size_t)(base + 2 * lq) * HDIM + 4 * v)     = ra;
            *(float4*)(op + (size_t)(base + 2 * lq + 1) * HDIM + 4 * v) = rb;
        }
    }
}

extern "C" void kernel_launch(void* const* d_in, const int* in_sizes, int n_in,
                              void* d_out, int out_size)
{
    const float* x   = (const float*)d_in[0];
    const float* res = (const float*)d_in[1];
    const int*   ax  = (const int*)d_in[2];
    const float* gp  = (const float*)d_in[3];
    float* out = (float*)d_out;

    const int n_img = in_sizes[1];   // 64
    // A2(4*553 half2 = 8848) + LOW(8192) + pos2(2048) + w(128) = 19216 B
    const size_t smem = (size_t)(4 * AS2) * 4 + (size_t)(HDIM * TW) * 2
                      + (size_t)HDIM * 4 + 32 * 4;

    cudaFuncSetAttribute(lowres_kernel,
                         cudaFuncAttributeMaxDynamicSharedMemorySize, (int)smem);

    dim3 grid((HDIM / TW) * n_img);  // 4096 CTAs, image-interleaved
    lowres_kernel<<<grid, NT, smem>>>(x, res, ax, gp, out);
}

// round 16
// speedup vs baseline: 1.0447x; 1.0447x over previous
#include <cuda_runtime.h>
#include <cuda_fp16.h>
#include <math.h>

// RandomLowRes2D fused kernel, v12: v11 + batched tap loads (MLP=16),
// combined down/up weights (2 accumulators), 64-reg budget (8 CTAs/SM).

#define HDIM 512
#define TW   8            // lanes (cross-axis) per CTA
#define HALO 16
#define AS2  553          // A pair-row stride in half2 units; 553 % 32 == 9
#define NT   128

__device__ __forceinline__ int refl(int t) {
    t = (t < 0) ? (-1 - t) : t;
    return (t >= HDIM) ? (2 * HDIM - 1 - t) : t;
}

// Fused blur+downsample. Task = (lane-pair q, low row j).
// low[j] = sum_k v[p1-R+k] * (f0*w0(k) + fr*w1(k)); taps batch-loaded (MLP=16).
template<int R>
__device__ __forceinline__ void blur_down(const __half2* __restrict__ A2,
                                          __half* __restrict__ LOW,
                                          const float* __restrict__ w,
                                          float inv_wsum, float res,
                                          int n_low, int tid)
{
    float wr[R + 1];
    if (R == 0) wr[0] = 1.0f;
    else {
        #pragma unroll
        for (int k = 0; k <= R; k++) wr[k] = w[15 - R + k] * inv_wsum;
    }
    constexpr int NTAP = 2 * R + 2;
    constexpr int CHNK = (NTAP > 16) ? 16 : NTAP;
    const int ntask = n_low * 4;
    for (int task = tid; task < ntask; task += NT) {
        int q = task & 3;
        int j = task >> 2;
        float pos = fminf((float)j * res, 511.0f);
        float lof = floorf(pos);
        float fr  = pos - lof;
        float f0  = 1.0f - fr;
        const __half2* Ap = A2 + q * AS2 + (HALO + (int)lof - R);
        float accx = 0.f, accy = 0.f;
        #pragma unroll
        for (int c0 = 0; c0 < NTAP; c0 += CHNK) {
            __half2 raw[CHNK];
            #pragma unroll
            for (int t = 0; t < CHNK; t++)
                if (c0 + t < NTAP) raw[t] = Ap[c0 + t];   // batched, imm offsets
            #pragma unroll
            for (int t = 0; t < CHNK; t++) {
                const int k = c0 + t;
                if (k >= NTAP) break;
                const float w0 = (k <= 2 * R) ? wr[(k <= R) ? k : 2 * R - k] : 0.f;
                const float w1 = (k >= 1)
                    ? wr[((k - 1) <= R) ? (k - 1) : 2 * R - (k - 1)] : 0.f;
                float wc = f0 * w0 + fr * w1;
                float2 v = __half22float2(raw[t]);
                accx = fmaf(wc, v.x, accx);
                accy = fmaf(wc, v.y, accy);
            }
        }
        *(__half2*)(LOW + j * TW + 2 * q) = __floats2half2_rn(accx, accy);
    }
}

__global__ __launch_bounds__(NT, 8)
void lowres_kernel(const float* __restrict__ x,
                   const float* __restrict__ resolution,
                   const int*   __restrict__ axis,
                   const float* __restrict__ gap,
                   float* __restrict__ out)
{
    extern __shared__ float dynsm[];
    __half2* A2   = (__half2*)dynsm;                 // [4][AS2] half2 (8848 B)
    __half*  A_h  = (__half*)A2;
    __half*  LOW  = (__half*)(A2 + 4 * AS2);         // [HDIM][8] fp16 (8192 B)
    float*   pos2 = (float*)(LOW + HDIM * TW);       // [HDIM]
    float*   w    = pos2 + HDIM;                     // [32]

    const int bid  = blockIdx.x;
    const int img  = bid & 63;          // interleave images across waves
    const int tile = bid >> 6;
    const int tid  = threadIdx.x;

    const float res = resolution[img];
    const int   ax  = axis[img];
    const float sig = fmaxf(res * gap[img] * 0.42466090014400953f, 1e-6f);
    const int   R   = (sig < 0.18f) ? 0 : (sig < 0.6f) ? 3 : (sig < 1.4f) ? 7 : 15;

    const int   n_low = (int)fmaxf(floorf(512.0f / res), 1.0f);
    const float nl1   = (float)(n_low - 1);

    if (tid < 31) {
        float e = (float)(tid - 15) / sig;
        w[tid] = expf(-0.5f * e * e);
    }
    for (int i = tid; i < HDIM; i += NT)
        pos2[i] = fminf((float)i / res, nl1);   // true division as reference

    const int base = tile * TW;
    const size_t ib = (size_t)img * HDIM * HDIM;
    const float* ip = x + ib;
    float*       op = out + ib;

    // ---- load slab into fp16 pair-major A (+ reflected halo) ----
    if (ax == 0) {
        const float4* ip4 = (const float4*)ip;
        for (int idx = tid; idx < HDIM * 2; idx += NT) {
            int l4 = idx & 1;                  // lanes 4*l4 .. 4*l4+3
            int p  = idx >> 1;
            float4 v = ip4[p * (HDIM / 4) + (base >> 2) + l4];
            int q0 = 2 * l4;
            A2[q0 * AS2 + HALO + p]       = __floats2half2_rn(v.x, v.y);
            A2[(q0 + 1) * AS2 + HALO + p] = __floats2half2_rn(v.z, v.w);
        }
    } else {
        // warp = 8 lanes x 4 col-groups: scalar half stores <=2-way
        for (int idx = tid; idx < TW * (HDIM / 4); idx += NT) {
            int l = idx & 7;
            int v = idx >> 3;
            float4 t = *(const float4*)(ip + (size_t)(base + l) * HDIM + 4 * v);
            int q = l >> 1, h = l & 1;
            #pragma unroll
            for (int i = 0; i < 4; i++) {
                int row = 4 * v + i + HALO;
                float val = (i == 0) ? t.x : (i == 1) ? t.y : (i == 2) ? t.z : t.w;
                A_h[(q * AS2 + row) * 2 + h] = __float2half(val);
            }
        }
    }
    for (int idx = tid; idx < 2 * HALO * TW; idx += NT) {   // 256 halo elems
        int l = idx & (TW - 1);
        int hh = idx >> 3;
        int t = (hh < HALO) ? (hh - HALO) : (HDIM + hh - HALO);
        int rt = refl(t);
        float val = (ax == 0) ? ip[rt * HDIM + base + l]
                              : ip[(size_t)(base + l) * HDIM + rt];
        A_h[((l >> 1) * AS2 + HALO + t) * 2 + (l & 1)] = __float2half(val);
    }
    __syncthreads();

    float inv_wsum = 1.0f;
    if (R > 0) {
        float s = 0.f;
        #pragma unroll
        for (int k = 0; k < 31; k++) s += w[k];
        inv_wsum = 1.0f / s;
    }

    // ---- fused blur + downsample -> LOW (fp16, pos-major) ----
    if      (R == 0)  blur_down<0>(A2, LOW, w, inv_wsum, res, n_low, tid);
    else if (R == 3)  blur_down<3>(A2, LOW, w, inv_wsum, res, n_low, tid);
    else if (R == 7)  blur_down<7>(A2, LOW, w, inv_wsum, res, n_low, tid);
    else              blur_down<15>(A2, LOW, w, inv_wsum, res, n_low, tid);
    __syncthreads();

    // ---- upsample + gmem stores ----
    if (ax == 0) {
        for (int i = tid; i < HDIM; i += NT) {
            float p2v = pos2[i];
            float l2  = floorf(p2v);
            float f   = p2v - l2;
            int j1 = min((int)l2, n_low - 1);
            int j2 = min(j1 + 1, n_low - 1);
            float omf = 1.0f - f;
            float4 r1 = *(const float4*)(LOW + j1 * TW);   // whole 8-lane row
            float4 r2 = *(const float4*)(LOW + j2 * TW);
            const __half2* h1 = (const __half2*)&r1;
            const __half2* h2 = (const __half2*)&r2;
            float4 o0, o1;
            {
                float2 a = __half22float2(h1[0]), b = __half22float2(h2[0]);
                o0.x = a.x * omf + b.x * f;  o0.y = a.y * omf + b.y * f;
                a = __half22float2(h1[1]); b = __half22float2(h2[1]);
                o0.z = a.x * omf + b.x * f;  o0.w = a.y * omf + b.y * f;
                a = __half22float2(h1[2]); b = __half22float2(h2[2]);
                o1.x = a.x * omf + b.x * f;  o1.y = a.y * omf + b.y * f;
                a = __half22float2(h1[3]); b = __half22float2(h2[3]);
                o1.z = a.x * omf + b.x * f;  o1.w = a.y * omf + b.y * f;
            }
            *(float4*)(op + (size_t)i * HDIM + base)     = o0;
            *(float4*)(op + (size_t)i * HDIM + base + 4) = o1;
        }
    } else {
        for (int idx = tid; idx < 4 * (HDIM / 4); idx += NT) {
            int v  = idx & 127;
            int lq = idx >> 7;              // 0..3 -> lanes 2lq, 2lq+1
            const float4 pv = *(const float4*)(pos2 + 4 * v);
            float4 ra, rb;
            #pragma unroll
            for (int q = 0; q < 4; q++) {
                float p2v = (q == 0) ? pv.x : (q == 1) ? pv.y : (q == 2) ? pv.z : pv.w;
                float l2  = floorf(p2v);
                float f   = p2v - l2;
                int j1 = min((int)l2, n_low - 1);
                int j2 = min(j1 + 1, n_low - 1);
                float2 h1 = __half22float2(*(const __half2*)(LOW + j1 * TW + 2 * lq));
                float2 h2 = __half22float2(*(const __half2*)(LOW + j2 * TW + 2 * lq));
                float va = h1.x * (1.0f - f) + h2.x * f;
                float vb = h1.y * (1.0f - f) + h2.y * f;
                if (q == 0) { ra.x = va; rb.x = vb; }
                else if (q == 1) { ra.y = va; rb.y = vb; }
                else if (q == 2) { ra.z = va; rb.z = vb; }
                else { ra.w = va; rb.w = vb; }
            }
            *(float4*)(op + (size_t)(base + 2 * lq) * HDIM + 4 * v)     = ra;
            *(float4*)(op + (size_t)(base + 2 * lq + 1) * HDIM + 4 * v) = rb;
        }
    }
}

extern "C" void kernel_launch(void* const* d_in, const int* in_sizes, int n_in,
                              void* d_out, int out_size)
{
    const float* x   = (const float*)d_in[0];
    const float* res = (const float*)d_in[1];
    const int*   ax  = (const int*)d_in[2];
    const float* gp  = (const float*)d_in[3];
    float* out = (float*)d_out;

    const int n_img = in_sizes[1];   // 64
    // A2(8848) + LOW(8192) + pos2(2048) + w(128) = 19216 B
    const size_t smem = (size_t)(4 * AS2) * 4 + (size_t)(HDIM * TW) * 2
                      + (size_t)HDIM * 4 + 32 * 4;

    cudaFuncSetAttribute(lowres_kernel,
                         cudaFuncAttributeMaxDynamicSharedMemorySize, (int)smem);

    dim3 grid((HDIM / TW) * n_img);  // 4096 CTAs, image-interleaved
    lowres_kernel<<<grid, NT, smem>>>(x, res, ax, gp, out);
}